// round 1
// baseline (speedup 1.0000x reference)
#include <cuda_runtime.h>
#include <math.h>

#define NB     32
#define NA     33600
#define K_TOP  1000
#define NBINS  8192
#define NSUB   2048
#define NCAND  2048

// scratch (static device globals — no allocation)
__device__ float g_scores[NB * NA];   // 4.3 MB, stays L2-resident
__device__ int   g_keep[NB * K_TOP];

// Bitwise match of XLA GPU logistic: 1/(1+exp(-x)), exp -> libdevice __nv_expf,
// division -> div.rn.f32 (nvcc defaults, no fast-math).
__device__ __forceinline__ float sigref(float x) {
    return 1.0f / (1.0f + expf(-x));
}

// ---------------------------------------------------------------------------
// Kernel 1: score[b, a] = sigmoid(cls) * sigmoid(obj)
// ---------------------------------------------------------------------------
__global__ void score_kernel(const float* __restrict__ cls0, const float* __restrict__ cls1,
                             const float* __restrict__ cls2,
                             const float* __restrict__ obj0, const float* __restrict__ obj1,
                             const float* __restrict__ obj2) {
    int i = blockIdx.x * blockDim.x + threadIdx.x;
    if (i >= NB * NA) return;
    int b = i / NA;
    int a = i - b * NA;
    float c, o;
    if (a < 25600)      { int p = a;         c = cls0[b * 25600 + p]; o = obj0[b * 25600 + p]; }
    else if (a < 32000) { int p = a - 25600; c = cls1[b * 6400  + p]; o = obj1[b * 6400  + p]; }
    else                { int p = a - 32000; c = cls2[b * 1600  + p]; o = obj2[b * 1600  + p]; }
    g_scores[i] = sigref(c) * sigref(o);
}

// ---------------------------------------------------------------------------
// Kernel 2: exact sorted top-1000 per batch (one CTA per batch, 1024 threads)
// ---------------------------------------------------------------------------

// Find threshold bin: largest bin T with count(bins > T) < K <= count(bins >= T).
// hist has nbins entries (nbins/1024 per thread), results in *s_bin / *s_above.
__device__ void find_thresh(unsigned int* hist, int nbins, int K, int tid,
                            int* wsum, int* s_bin, int* s_above) {
    int per  = nbins >> 10;
    int base = nbins - 1 - tid * per;
    int tsum = 0;
#pragma unroll 4
    for (int q = 0; q < per; q++) tsum += (int)hist[base - q];

    // block exclusive scan over threads (descending-bin order)
    int lane = tid & 31, wid = tid >> 5;
    int x = tsum;
#pragma unroll
    for (int d = 1; d < 32; d <<= 1) {
        int n = __shfl_up_sync(0xffffffffu, x, d);
        if (lane >= d) x += n;
    }
    if (lane == 31) wsum[wid] = x;
    __syncthreads();
    if (wid == 0) {
        int w = wsum[lane];
#pragma unroll
        for (int d = 1; d < 32; d <<= 1) {
            int n = __shfl_up_sync(0xffffffffu, w, d);
            if (lane >= d) w += n;
        }
        wsum[lane] = w;
    }
    __syncthreads();
    int excl = (wid == 0 ? 0 : wsum[wid - 1]) + (x - tsum);

    if (excl < K && excl + tsum >= K) {     // exactly one thread
        int c = excl;
        for (int q = 0; q < per; q++) {
            int bin = base - q;
            int h = (int)hist[bin];
            if (c + h >= K) { *s_bin = bin; *s_above = c; break; }
            c += h;
        }
    }
    __syncthreads();
}

__global__ __launch_bounds__(1024) void topk_kernel(float* __restrict__ dout) {
    __shared__ unsigned int hist[NBINS];          // 32 KB, reused as candidate buffer
    __shared__ int  wsum[32];
    __shared__ int  s_bin, s_above;
    __shared__ unsigned int s_cnt;
    unsigned long long* cand = (unsigned long long*)hist;

    int b = blockIdx.x;
    int tid = threadIdx.x;
    const float* sc = g_scores + b * NA;

    // Phase 1: coarse histogram on score bits >> 17 (scores in (0,1) -> bin < 8128)
    for (int q = tid; q < NBINS; q += 1024) hist[q] = 0u;
    __syncthreads();
    for (int a = tid; a < NA; a += 1024) {
        unsigned int bits = __float_as_uint(sc[a]);
        atomicAdd(&hist[bits >> 17], 1u);
    }
    __syncthreads();
    find_thresh(hist, NBINS, K_TOP, tid, wsum, &s_bin, &s_above);
    int T = s_bin;
    int need2 = K_TOP - s_above;
    __syncthreads();

    // Phase 2: refine within bin T with 2048 sub-bins on bits[16:6]
    for (int q = tid; q < NSUB; q += 1024) hist[q] = 0u;
    __syncthreads();
    for (int a = tid; a < NA; a += 1024) {
        unsigned int bits = __float_as_uint(sc[a]);
        if ((int)(bits >> 17) == T) atomicAdd(&hist[(bits >> 6) & 2047u], 1u);
    }
    __syncthreads();
    find_thresh(hist, NSUB, need2, tid, wsum, &s_bin, &s_above);
    unsigned int cut = ((unsigned int)T << 17) | ((unsigned int)s_bin << 6);
    __syncthreads();

    // Phase 3: compact candidates (bits >= cut) into smem as sortable 64-bit keys.
    // key = (score_bits << 32) | (~index) : descending sort == descending score,
    // ties broken by ascending index (jax top_k stability).
    if (tid == 0) s_cnt = 0u;
    __syncthreads();
    for (int a = tid; a < NA; a += 1024) {
        unsigned int bits = __float_as_uint(sc[a]);
        if (bits >= cut) {
            unsigned int pos = atomicAdd(&s_cnt, 1u);
            if (pos < NCAND)
                cand[pos] = ((unsigned long long)bits << 32) |
                            (unsigned long long)(0xFFFFFFFFu - (unsigned int)a);
        }
    }
    __syncthreads();
    int cnt = (int)s_cnt; if (cnt > NCAND) cnt = NCAND;
    for (int q = cnt + tid; q < NCAND; q += 1024) cand[q] = 0ull;
    __syncthreads();

    // Phase 4: bitonic sort 2048 keys, descending
    for (unsigned int k = 2; k <= NCAND; k <<= 1) {
        for (unsigned int j = k >> 1; j > 0; j >>= 1) {
            for (unsigned int i = tid; i < NCAND; i += 1024) {
                unsigned int ixj = i ^ j;
                if (ixj > i) {
                    unsigned long long A = cand[i], B = cand[ixj];
                    bool desc = ((i & k) == 0);
                    if (desc ? (A < B) : (A > B)) { cand[i] = B; cand[ixj] = A; }
                }
            }
            __syncthreads();
        }
    }

    // Phase 5: emit kept indices + score column of dets
    if (tid < K_TOP) {
        unsigned long long key = cand[tid];
        unsigned int bits = (unsigned int)(key >> 32);
        unsigned int a    = 0xFFFFFFFFu - (unsigned int)(key & 0xFFFFFFFFull);
        g_keep[b * K_TOP + tid] = (int)a;
        dout[b * (K_TOP * 5) + tid * 5 + 4] = __uint_as_float(bits);
    }
}

// ---------------------------------------------------------------------------
// Kernel 3: decode kept anchors. 18 tasks per detection: 17 kpts + 1 bbox.
// ---------------------------------------------------------------------------
__global__ void decode_kernel(const float* __restrict__ bbox0, const float* __restrict__ bbox1,
                              const float* __restrict__ bbox2,
                              const float* __restrict__ kpt0,  const float* __restrict__ kpt1,
                              const float* __restrict__ kpt2,
                              const float* __restrict__ vis0,  const float* __restrict__ vis1,
                              const float* __restrict__ vis2,
                              float* __restrict__ dout) {
    const int NTASK = NB * K_TOP * 18;
    int task = blockIdx.x * blockDim.x + threadIdx.x;
    if (task >= NTASK) return;
    int det = task / 18;
    int sub = task - det * 18;
    int b   = det / K_TOP;
    int a   = g_keep[det];

    int p, HW, l;
    float s, px, py;
    if (a < 25600)      { p = a;         HW = 25600; s = 8.0f;  l = 0; px = (float)(p % 160) * 8.0f;  py = (float)(p / 160) * 8.0f;  }
    else if (a < 32000) { p = a - 25600; HW = 6400;  s = 16.0f; l = 1; px = (float)(p % 80)  * 16.0f; py = (float)(p / 80)  * 16.0f; }
    else                { p = a - 32000; HW = 1600;  s = 32.0f; l = 2; px = (float)(p % 40)  * 32.0f; py = (float)(p / 40)  * 32.0f; }

    if (sub < 17) {
        int k = sub;
        const float* kp = (l == 0) ? kpt0 : (l == 1) ? kpt1 : kpt2;
        const float* vp = (l == 0) ? vis0 : (l == 1) ? vis1 : vis2;
        float kx = kp[(b * 34 + 2 * k)     * HW + p];
        float ky = kp[(b * 34 + 2 * k + 1) * HW + p];
        float v  = vp[(b * 17 + k)         * HW + p];
        int off = NB * K_TOP * 5 + det * 51 + k * 3;
        dout[off + 0] = kx * s + px;
        dout[off + 1] = ky * s + py;
        dout[off + 2] = sigref(v);
    } else {
        const float* bp = (l == 0) ? bbox0 : (l == 1) ? bbox1 : bbox2;
        float bx = bp[(b * 4 + 0) * HW + p];
        float by = bp[(b * 4 + 1) * HW + p];
        float bw = bp[(b * 4 + 2) * HW + p];
        float bh = bp[(b * 4 + 3) * HW + p];
        float x  = bx * s + px;
        float y  = by * s + py;
        float hw = expf(bw) * s * 0.5f;
        float hh = expf(bh) * s * 0.5f;
        int off = det * 5;
        dout[off + 0] = x - hw;
        dout[off + 1] = y - hh;
        dout[off + 2] = x + hw;
        dout[off + 3] = y + hh;
    }
}

// ---------------------------------------------------------------------------
extern "C" void kernel_launch(void* const* d_in, const int* in_sizes, int n_in,
                              void* d_out, int out_size) {
    const float* cls0  = (const float*)d_in[0];
    const float* cls1  = (const float*)d_in[1];
    const float* cls2  = (const float*)d_in[2];
    const float* bbox0 = (const float*)d_in[3];
    const float* bbox1 = (const float*)d_in[4];
    const float* bbox2 = (const float*)d_in[5];
    const float* obj0  = (const float*)d_in[6];
    const float* obj1  = (const float*)d_in[7];
    const float* obj2  = (const float*)d_in[8];
    const float* kpt0  = (const float*)d_in[9];
    const float* kpt1  = (const float*)d_in[10];
    const float* kpt2  = (const float*)d_in[11];
    const float* vis0  = (const float*)d_in[12];
    const float* vis1  = (const float*)d_in[13];
    const float* vis2  = (const float*)d_in[14];
    float* dout = (float*)d_out;

    score_kernel<<<(NB * NA + 255) / 256, 256>>>(cls0, cls1, cls2, obj0, obj1, obj2);
    topk_kernel<<<NB, 1024>>>(dout);
    decode_kernel<<<(NB * K_TOP * 18 + 255) / 256, 256>>>(bbox0, bbox1, bbox2,
                                                          kpt0, kpt1, kpt2,
                                                          vis0, vis1, vis2, dout);
}